// round 6
// baseline (speedup 1.0000x reference)
#include <cuda_runtime.h>
#include <cuda_bf16.h>

// Dconv: x[8,32,224,224] f32, W[1,8,3,3], Bv[8]
// out[b, f*32+c, ho, wo] = sum_{i,j} x[b,c,ho+i,wo+j]*W[0,f,i,j] + Bv[f]
// out [8, 256, 222, 222] f32 (~404 MB) -> HBM-store-bound.
//
// R5: weights in registers (loaded once/thread), rolling 3-row input window,
// 8 outputs x 6 rows per thread, fma.rn.f32x2 throughout, zero smem/barriers.

#define KFMA2(d, a, b, c) \
    asm("fma.rn.f32x2 %0, %1, %2, %3;" : "=l"(d) : "l"(a), "l"(b), "l"(c))
#define KPACK2(d, lo, hi) \
    asm("mov.b64 %0, {%1, %2};" : "=l"(d) \
        : "r"(__float_as_uint(lo)), "r"(__float_as_uint(hi)))

typedef unsigned long long ull;

static constexpr int Hc   = 224;
static constexpr int Ho   = 222;
static constexpr int C    = 32;
static constexpr int NF   = 8;
static constexpr int ROWS = 6;                 // output rows per thread
static constexpr int IN_PLANE  = Hc * Hc;      // 50176
static constexpr int OUT_PLANE = Ho * Ho;      // 49284

// Load one input row (10 floats -> 9 overlapping f32x2 pairs).
// edge lane: cols 8,9 of the window are OOB -> zero (only feed unstored outputs).
__device__ __forceinline__ void load_row(ull pr[9], const float* rp, bool edge)
{
    float4 a = *reinterpret_cast<const float4*>(rp);
    float4 b = *reinterpret_cast<const float4*>(rp + 4);
    float cx = 0.0f, cy = 0.0f;
    if (!edge) {
        float2 c2 = *reinterpret_cast<const float2*>(rp + 8);
        cx = c2.x; cy = c2.y;
    }
    KPACK2(pr[0], a.x, a.y);
    KPACK2(pr[1], a.y, a.z);
    KPACK2(pr[2], a.z, a.w);
    KPACK2(pr[3], a.w, b.x);
    KPACK2(pr[4], b.x, b.y);
    KPACK2(pr[5], b.y, b.z);
    KPACK2(pr[6], b.z, b.w);
    KPACK2(pr[7], b.w, cx);
    KPACK2(pr[8], cx, cy);
}

__global__ __launch_bounds__(256, 2)
void dconv_r5_kernel(const float* __restrict__ x,
                     const float* __restrict__ W,
                     const float* __restrict__ Bv,
                     float* __restrict__ out)
{
    const int tx = threadIdx.x;        // wo group
    const int f  = threadIdx.y;        // filter
    if (tx >= 28) return;              // 28*8 = 224 >= 222 cols

    // ---- weights & bias -> registers (once per thread) ----
    ull w[9];
    #pragma unroll
    for (int t = 0; t < 9; t++) {
        float wv = __ldg(&W[f * 9 + t]);
        KPACK2(w[t], wv, wv);
    }
    ull bpair;
    {
        float bv = __ldg(&Bv[f]);
        KPACK2(bpair, bv, bv);
    }

    const int p    = blockIdx.y;                 // plane = b*32 + c
    const int ho0  = blockIdx.x * ROWS;          // 37 tiles * 6 = 222
    const int wo0  = tx * 8;
    const bool edge = (tx == 27);                // outputs 216..221 only

    const float* xp = x + (size_t)p * IN_PLANE + (size_t)ho0 * Hc + wo0;

    const int b = p >> 5;
    const int c = p & 31;
    float* op = out + ((size_t)(b * (NF * C) + f * C + c) * Ho + ho0) * Ho + wo0;

    // ---- rolling 3-row window ----
    ull win[3][9];
    load_row(win[0], xp, edge); xp += Hc;
    load_row(win[1], xp, edge); xp += Hc;

    #pragma unroll
    for (int it = 0; it < ROWS; it++) {
        load_row(win[(it + 2) % 3], xp, edge); xp += Hc;

        ull acc[4];
        acc[0] = bpair; acc[1] = bpair; acc[2] = bpair; acc[3] = bpair;

        #pragma unroll
        for (int r = 0; r < 3; r++) {
            const ull* row = win[(it + r) % 3];
            #pragma unroll
            for (int j = 0; j < 3; j++) {
                ull wt = w[r * 3 + j];
                KFMA2(acc[0], row[0 + j], wt, acc[0]);
                KFMA2(acc[1], row[2 + j], wt, acc[1]);
                KFMA2(acc[2], row[4 + j], wt, acc[2]);
                KFMA2(acc[3], row[6 + j], wt, acc[3]);
            }
        }

        *reinterpret_cast<float2*>(op + 0) = *reinterpret_cast<float2*>(&acc[0]);
        *reinterpret_cast<float2*>(op + 2) = *reinterpret_cast<float2*>(&acc[1]);
        *reinterpret_cast<float2*>(op + 4) = *reinterpret_cast<float2*>(&acc[2]);
        if (!edge)
            *reinterpret_cast<float2*>(op + 6) = *reinterpret_cast<float2*>(&acc[3]);
        op += Ho;
    }
}

extern "C" void kernel_launch(void* const* d_in, const int* in_sizes, int n_in,
                              void* d_out, int out_size)
{
    const float* x  = (const float*)d_in[0];
    const float* W  = (const float*)d_in[1];
    const float* Bv = (const float*)d_in[2];
    float* out = (float*)d_out;

    dim3 block(32, 8);                 // warp = one filter, lanes 0..27 active
    dim3 grid(Ho / ROWS, NF * C);      // (37 row-tiles, 256 planes)
    dconv_r5_kernel<<<grid, block>>>(x, W, Bv, out);
}

// round 7
// speedup vs baseline: 1.9984x; 1.9984x over previous
#include <cuda_runtime.h>
#include <cuda_bf16.h>

// Dconv: x[8,32,224,224] f32, W[1,8,3,3], Bv[8]
// out[b, f*32+c, ho, wo] = sum_{i,j} x[b,c,ho+i,wo+j]*W[0,f,i,j] + Bv[f]
// out [8, 256, 222, 222] f32 (~404 MB) -> HBM-store-bound.
//
// R6: R4 structure (thread = 4 wo, all 8 filters, smem {w,w} weights) but
// 2 output rows per thread: each weight LDS feeds 4 accumulators, halving
// weight-LDS traffic per output; 4-row input window loaded once, middle
// rows reused vertically in registers.

#define KFMA2(d, a, b, c) \
    asm("fma.rn.f32x2 %0, %1, %2, %3;" : "=l"(d) : "l"(a), "l"(b), "l"(c))
#define KPACK2(d, lo, hi) \
    asm("mov.b64 %0, {%1, %2};" : "=l"(d) \
        : "r"(__float_as_uint(lo)), "r"(__float_as_uint(hi)))

typedef unsigned long long ull;

static constexpr int Hc   = 224;
static constexpr int Ho   = 222;
static constexpr int C    = 32;
static constexpr int NF   = 8;
static constexpr int IN_PLANE  = Hc * Hc;       // 50176
static constexpr int OUT_PLANE = Ho * Ho;       // 49284

__global__ __launch_bounds__(256)
void dconv_r6_kernel(const float* __restrict__ x,
                     const float* __restrict__ W,
                     const float* __restrict__ Bv,
                     float* __restrict__ out)
{
    __shared__ ull s_w[NF * 9];   // {w,w} packed f32x2
    __shared__ ull s_b[NF];       // {bv,bv}

    const int tid = threadIdx.y * 32 + threadIdx.x;
    if (tid < NF * 9) {
        float w = W[tid];
        ull pw; KPACK2(pw, w, w);
        s_w[tid] = pw;
    } else if (tid < NF * 9 + NF) {
        float bv = Bv[tid - NF * 9];
        ull pb; KPACK2(pb, bv, bv);
        s_b[tid - NF * 9] = pb;
    }
    __syncthreads();

    const int gx = blockIdx.x * 32 + threadIdx.x;   // wo group index
    if (gx >= 56) return;                           // 56*4 = 224 >= 222
    const int wo0 = gx * 4;

    const int hp = blockIdx.y * 8 + threadIdx.y;    // row-pair index
    if (hp >= 111) return;                          // 111*2 = 222
    const int ho0 = hp * 2;

    const int p = blockIdx.z;                       // plane = b*32 + c

    // ---- load 4 input rows x 6 cols into registers ----
    const float* xp = x + (size_t)p * IN_PLANE + (size_t)ho0 * Hc + wo0;
    float in[4][6];
    if (wo0 <= Ho - 4) {            // wo0 <= 218: cols wo0..wo0+5 <= 223 in-bounds
        #pragma unroll
        for (int r = 0; r < 4; r++) {
            const float* rp = xp + r * Hc;
            float4 a  = *reinterpret_cast<const float4*>(rp);
            float2 b2 = *reinterpret_cast<const float2*>(rp + 4);
            in[r][0] = a.x;  in[r][1] = a.y;  in[r][2] = a.z;
            in[r][3] = a.w;  in[r][4] = b2.x; in[r][5] = b2.y;
        }
    } else {                        // wo0 == 220: cols 224,225 OOB
        #pragma unroll
        for (int r = 0; r < 4; r++) {
            const float* rp = xp + r * Hc;
            float4 a = *reinterpret_cast<const float4*>(rp);
            in[r][0] = a.x; in[r][1] = a.y; in[r][2] = a.z; in[r][3] = a.w;
            in[r][4] = 0.0f; in[r][5] = 0.0f;
        }
    }

    // ---- pack overlapping pixel pairs: q0 = (j,j+1), q1 = (j+2,j+3) ----
    ull q0[4][3], q1[4][3];
    #pragma unroll
    for (int r = 0; r < 4; r++) {
        #pragma unroll
        for (int j = 0; j < 3; j++) {
            KPACK2(q0[r][j], in[r][j],     in[r][j + 1]);
            KPACK2(q1[r][j], in[r][j + 2], in[r][j + 3]);
        }
    }

    const bool full = (wo0 <= Ho - 4);   // second pair (cols wo0+2,+3) storable?
    const int  b = p >> 5;
    const int  c = p & 31;
    float* obase = out + ((size_t)(b * (NF * C) + c) * Ho + ho0) * Ho + wo0;

    #pragma unroll
    for (int f = 0; f < NF; f++) {
        ull a0 = s_b[f], a1 = s_b[f];    // row ho0,   pairs 0 / 1
        ull b0 = s_b[f], b1 = s_b[f];    // row ho0+1, pairs 0 / 1
        #pragma unroll
        for (int r = 0; r < 3; r++) {
            #pragma unroll
            for (int j = 0; j < 3; j++) {
                ull wt = s_w[f * 9 + r * 3 + j];
                KFMA2(a0, q0[r][j],     wt, a0);
                KFMA2(a1, q1[r][j],     wt, a1);
                KFMA2(b0, q0[r + 1][j], wt, b0);
                KFMA2(b1, q1[r + 1][j], wt, b1);
            }
        }
        float* op = obase + (size_t)f * (C * OUT_PLANE);
        *reinterpret_cast<float2*>(op)          = *reinterpret_cast<float2*>(&a0);
        *reinterpret_cast<float2*>(op + Ho)     = *reinterpret_cast<float2*>(&b0);
        if (full) {
            *reinterpret_cast<float2*>(op + 2)      = *reinterpret_cast<float2*>(&a1);
            *reinterpret_cast<float2*>(op + Ho + 2) = *reinterpret_cast<float2*>(&b1);
        }
    }
}

extern "C" void kernel_launch(void* const* d_in, const int* in_sizes, int n_in,
                              void* d_out, int out_size)
{
    const float* x  = (const float*)d_in[0];
    const float* W  = (const float*)d_in[1];
    const float* Bv = (const float*)d_in[2];
    float* out = (float*)d_out;

    dim3 block(32, 8);                  // 256 threads
    dim3 grid(2, 14, NF * C);           // 56 wo-groups, 112 row-pairs, 256 planes
    dconv_r6_kernel<<<grid, block>>>(x, W, Bv, out);
}

// round 8
// speedup vs baseline: 2.6955x; 1.3488x over previous
#include <cuda_runtime.h>
#include <cuda_bf16.h>

// Dconv: x[8,32,224,224] f32, W[1,8,3,3], Bv[8]
// out[b, f*32+c, ho, wo] = sum_{i,j} x[b,c,ho+i,wo+j]*W[0,f,i,j] + Bv[f]
// out [8, 256, 222, 222] f32 (~404 MB) -> HBM-store-bound.
//
// R7: lane = one wo-pair (fully coalesced STG.64), 3 output rows/thread
// (74*3 = 222, zero row guards), LDS.128-vectorized {w,w} weight table,
// fma.rn.f32x2 throughout. __launch_bounds__(256,4) to keep 4 CTAs/SM.

#define KFMA2(d, a, b, c) \
    asm("fma.rn.f32x2 %0, %1, %2, %3;" : "=l"(d) : "l"(a), "l"(b), "l"(c))
#define KPACK2(d, lo, hi) \
    asm("mov.b64 %0, {%1, %2};" : "=l"(d) \
        : "r"(__float_as_uint(lo)), "r"(__float_as_uint(hi)))

typedef unsigned long long ull;

static constexpr int Hc   = 224;
static constexpr int Ho   = 222;
static constexpr int C    = 32;
static constexpr int NF   = 8;
static constexpr int IN_PLANE  = Hc * Hc;       // 50176
static constexpr int OUT_PLANE = Ho * Ho;       // 49284

__global__ __launch_bounds__(256, 4)
void dconv_r7_kernel(const float* __restrict__ x,
                     const float* __restrict__ W,
                     const float* __restrict__ Bv,
                     float* __restrict__ out)
{
    // per filter: [bias, w0..w8] as {v,v} pairs -> 10 ull = 80B (16B-multiple)
    __shared__ __align__(16) ull s_wb[NF][10];

    const int tid = threadIdx.y * 32 + threadIdx.x;
    if (tid < NF * 10) {
        const int f = tid / 10;
        const int k = tid % 10;
        float v = (k == 0) ? Bv[f] : W[f * 9 + (k - 1)];
        ull pv; KPACK2(pv, v, v);
        s_wb[f][k] = pv;
    }
    __syncthreads();

    // tile = 296 tiles total: (wo_tile in [0,4)) x (row_tile in [0,74))
    const int tile   = blockIdx.x * 8 + threadIdx.y;   // 37*8 = 296 exactly
    const int wo_t   = tile & 3;
    const int row_t  = tile >> 2;                      // 0..73
    const int lane   = threadIdx.x;

    const int wo0 = wo_t * 64 + lane * 2;              // this thread's output pair
    if (wo0 > Ho - 2) return;                          // idle lanes in wo_t==3
    const int ho0 = row_t * 3;                         // rows ho0..ho0+2, all < 222

    const int p = blockIdx.z;                          // plane = b*32 + c

    // ---- 5-row input window, 4 cols each -> 3 overlapping pairs per row ----
    const float* xp = x + (size_t)p * IN_PLANE + (size_t)ho0 * Hc + wo0;
    ull pr[5][3];
    #pragma unroll
    for (int r = 0; r < 5; r++) {
        const float* rp = xp + r * Hc;                 // rows ho0..ho0+4 <= 223
        float2 a = *reinterpret_cast<const float2*>(rp);
        float2 b = *reinterpret_cast<const float2*>(rp + 2);
        KPACK2(pr[r][0], a.x, a.y);
        KPACK2(pr[r][1], a.y, b.x);
        KPACK2(pr[r][2], b.x, b.y);
    }

    const int bq = p >> 5;
    const int c  = p & 31;
    float* obase = out + ((size_t)(bq * (NF * C) + c) * Ho + ho0) * Ho + wo0;

    #pragma unroll
    for (int f = 0; f < NF; f++) {
        const ulonglong2* wb = reinterpret_cast<const ulonglong2*>(&s_wb[f][0]);
        ulonglong2 v0 = wb[0];       // {bias, w0}
        ulonglong2 v1 = wb[1];       // {w1, w2}
        ulonglong2 v2 = wb[2];       // {w3, w4}
        ulonglong2 v3 = wb[3];       // {w5, w6}
        ulonglong2 v4 = wb[4];       // {w7, w8}
        ull w[9] = { v0.y, v1.x, v1.y, v2.x, v2.y, v3.x, v3.y, v4.x, v4.y };

        ull acc0 = v0.x, acc1 = v0.x, acc2 = v0.x;     // 3 output rows
        #pragma unroll
        for (int kr = 0; kr < 3; kr++) {
            #pragma unroll
            for (int kj = 0; kj < 3; kj++) {
                ull wt = w[kr * 3 + kj];
                KFMA2(acc0, pr[kr + 0][kj], wt, acc0);
                KFMA2(acc1, pr[kr + 1][kj], wt, acc1);
                KFMA2(acc2, pr[kr + 2][kj], wt, acc2);
            }
        }

        float* op = obase + (size_t)f * (C * OUT_PLANE);
        *reinterpret_cast<float2*>(op)          = *reinterpret_cast<float2*>(&acc0);
        *reinterpret_cast<float2*>(op + Ho)     = *reinterpret_cast<float2*>(&acc1);
        *reinterpret_cast<float2*>(op + 2 * Ho) = *reinterpret_cast<float2*>(&acc2);
    }
}

extern "C" void kernel_launch(void* const* d_in, const int* in_sizes, int n_in,
                              void* d_out, int out_size)
{
    const float* x  = (const float*)d_in[0];
    const float* W  = (const float*)d_in[1];
    const float* Bv = (const float*)d_in[2];
    float* out = (float*)d_out;

    dim3 block(32, 8);                  // warp = one (wo_tile,row_tile)
    dim3 grid(37, 1, NF * C);           // 37*8 = 296 tiles, 256 planes
    dconv_r7_kernel<<<grid, block>>>(x, W, Bv, out);
}